// round 1
// baseline (speedup 1.0000x reference)
#include <cuda_runtime.h>
#include <cstdint>

// Problem constants (fixed by the dataset)
#define MAXN 10000
#define KNBR 16
#define FDIM 64
#define HDIM 128

// ---------------- scratch (no allocations allowed) ----------------
__device__ int   g_nidx[MAXN * KNBR];
__device__ float g_dsq [MAXN * KNBR];
__device__ int   g_selfi[MAXN];
__device__ float g_esum[MAXN * HDIM];

// ---------------- helpers ----------------
__device__ __forceinline__ unsigned long long pk2(float lo, float hi) {
    unsigned long long r;
    asm("mov.b64 %0, {%1, %2};" : "=l"(r) : "f"(lo), "f"(hi));
    return r;
}
__device__ __forceinline__ void upk2(unsigned long long v, float& lo, float& hi) {
    asm("mov.b64 {%0, %1}, %2;" : "=f"(lo), "=f"(hi) : "l"(v));
}
__device__ __forceinline__ void fma2(unsigned long long& d, unsigned long long a, unsigned long long b) {
    asm("fma.rn.f32x2 %0, %1, %2, %0;" : "+l"(d) : "l"(a), "l"(b));
}
__device__ __forceinline__ float selu_f(float x) {
    const float sc = 1.0507009873554805f;
    const float al = 1.6732632423543772f;
    return x > 0.f ? sc * x : sc * al * expm1f(x);
}

// ---------------- KNN: one warp per row, exact (d2, idx) ordering ----------------
#define KNN_WARPS 8
__global__ void knn_kernel(const float* __restrict__ coords,
                           const int* __restrict__ rs, int nrs, int N,
                           float* __restrict__ out_nidx_f, float* __restrict__ out_d)
{
    __shared__ unsigned long long mg[KNN_WARPS][17 * 32];
    const int w    = threadIdx.x >> 5;
    const int lane = threadIdx.x & 31;
    const int row  = blockIdx.x * KNN_WARPS + w;
    if (row >= N) return;

    int s0 = 0, s1 = N;
    for (int s = 0; s + 1 < nrs; ++s) {
        int a = rs[s], b = rs[s + 1];
        if (a <= row && row < b) { s0 = a; s1 = b; }
    }

    const float xi = coords[row * 3 + 0];
    const float yi = coords[row * 3 + 1];
    const float zi = coords[row * 3 + 2];
    const float ni = __fadd_rn(__fadd_rn(__fmul_rn(xi, xi), __fmul_rn(yi, yi)), __fmul_rn(zi, zi));

    unsigned long long a[17];
#pragma unroll
    for (int t = 0; t < 17; ++t) a[t] = 0xFFFFFFFFFFFFFFFFull;

    for (int j = s0 + lane; j < s1; j += 32) {
        const float xj = coords[j * 3 + 0];
        const float yj = coords[j * 3 + 1];
        const float zj = coords[j * 3 + 2];
        const float nj  = __fadd_rn(__fadd_rn(__fmul_rn(xj, xj), __fmul_rn(yj, yj)), __fmul_rn(zj, zj));
        const float dot = __fadd_rn(__fadd_rn(__fmul_rn(xi, xj), __fmul_rn(yi, yj)), __fmul_rn(zi, zj));
        float d2 = __fadd_rn(__fadd_rn(ni, nj), __fmul_rn(-2.f, dot));
        d2 = fmaxf(d2, 0.f);
        unsigned long long key =
            ((unsigned long long)__float_as_uint(d2) << 32) | (unsigned)j;
        if (key < a[16]) {
            unsigned long long cur = key;
#pragma unroll
            for (int t = 0; t < 17; ++t) {
                if (cur < a[t]) { unsigned long long tmp = a[t]; a[t] = cur; cur = tmp; }
            }
        }
    }

#pragma unroll
    for (int t = 0; t < 17; ++t) mg[w][lane * 17 + t] = a[t];
    __syncwarp();

    int head = 0;
    for (int t = 0; t < 17; ++t) {
        unsigned long long v = mg[w][lane * 17 + head];
        unsigned long long m = v;
#pragma unroll
        for (int off = 16; off >= 1; off >>= 1) {
            unsigned long long o = __shfl_xor_sync(0xffffffffu, m, off);
            if (o < m) m = o;
        }
        unsigned ball = __ballot_sync(0xffffffffu, v == m);
        int win = __ffs(ball) - 1;
        if (lane == win) head++;
        if (lane == 0) {
            unsigned jj = (unsigned)(m & 0xffffffffu);
            float dd = __uint_as_float((unsigned)(m >> 32));
            if (t == 0) {
                g_selfi[row] = (int)jj;
            } else {
                g_nidx[row * KNBR + t - 1] = (int)jj;
                g_dsq [row * KNBR + t - 1] = dd;
                out_nidx_f[row * KNBR + t - 1] = (float)(int)jj;
                out_d    [row * KNBR + t - 1] = dd;
            }
        }
    }
}

// ---------------- block GEMM (f32x2 packed), operands in smem ----------------
// Computes O[m][n0..n0+7] for 128-col output; A [M x kp] (lda), W [kp x 128] smem,
// bias[128] smem, optional SELU. 256 threads: 16x16 grid, RPT rows x 8 cols/thread.
template<int RPT, bool DO_SELU>
__device__ __forceinline__ void gemm_block(const float* __restrict__ A, int lda,
                                           const float* __restrict__ W,
                                           const float* __restrict__ bias,
                                           float* __restrict__ O, int ldo,
                                           int kp, int valid)
{
    const int tx = threadIdx.x & 15;
    const int ty = threadIdx.x >> 4;
    const int n0 = tx * 8;
    const int m0 = ty * RPT;

    unsigned long long acc[RPT][4];
#pragma unroll
    for (int i = 0; i < RPT; ++i)
#pragma unroll
        for (int j = 0; j < 4; ++j)
            acc[i][j] = pk2(bias[n0 + 2 * j], bias[n0 + 2 * j + 1]);

    const float* Ap = A + m0 * lda;
    for (int k = 0; k < kp; k += 4) {
        float4 av[RPT];
#pragma unroll
        for (int i = 0; i < RPT; ++i)
            av[i] = *reinterpret_cast<const float4*>(Ap + i * lda + k);
#pragma unroll
        for (int r = 0; r < 4; ++r) {
            const float* wr = W + (k + r) * 128 + n0;
            ulonglong2 b0 = *reinterpret_cast<const ulonglong2*>(wr);
            ulonglong2 b1 = *reinterpret_cast<const ulonglong2*>(wr + 4);
#pragma unroll
            for (int i = 0; i < RPT; ++i) {
                float a_ = (r == 0) ? av[i].x : (r == 1) ? av[i].y : (r == 2) ? av[i].z : av[i].w;
                unsigned long long aa = pk2(a_, a_);
                fma2(acc[i][0], aa, b0.x);
                fma2(acc[i][1], aa, b0.y);
                fma2(acc[i][2], aa, b1.x);
                fma2(acc[i][3], aa, b1.y);
            }
        }
    }

#pragma unroll
    for (int i = 0; i < RPT; ++i) {
        int row = m0 + i;
        if (row < valid) {
            float o[8];
#pragma unroll
            for (int j = 0; j < 4; ++j) { upk2(acc[i][j], o[2 * j], o[2 * j + 1]); }
            if (DO_SELU) {
#pragma unroll
                for (int j = 0; j < 8; ++j) o[j] = selu_f(o[j]);
            }
            *reinterpret_cast<float4*>(O + row * ldo + n0)     = make_float4(o[0], o[1], o[2], o[3]);
            *reinterpret_cast<float4*>(O + row * ldo + n0 + 4) = make_float4(o[4], o[5], o[6], o[7]);
        }
    }
}

__device__ __forceinline__ void load_w(float* Wb, const float* __restrict__ Wg, int rows, int kp)
{
    const int tid = threadIdx.x;
    const int n4 = (rows * 128) >> 2;
    for (int i = tid; i < n4; i += 256)
        reinterpret_cast<float4*>(Wb)[i] = reinterpret_cast<const float4*>(Wg)[i];
    for (int i = tid; i < (kp - rows) * 128; i += 256)
        Wb[rows * 128 + i] = 0.f;
}

// ---------------- edge kernel: 8 nodes (128 edges) per block ----------------
#define EDGE_SMEM ((128*132*2 + 132*128 + 128*3) * 4)
__global__ void __launch_bounds__(256, 1)
edge_kernel(const float* __restrict__ h, const float* __restrict__ coords,
            const float* __restrict__ We1, const float* __restrict__ be1,
            const float* __restrict__ We2, const float* __restrict__ be2,
            const float* __restrict__ Wc1, const float* __restrict__ bc1,
            const float* __restrict__ Wc2, const float* __restrict__ bc2,
            float* __restrict__ coords_out, int N)
{
    extern __shared__ float sm[];
    float* bufA = sm;                 // 128 x 132
    float* bufB = bufA + 128 * 132;   // 128 x 132
    float* Wb   = bufB + 128 * 132;   // 132 x 128
    float* bias = Wb + 132 * 128;     // 128
    float* wc2  = bias + 128;         // 128
    float* wsh  = wc2 + 128;          // 128

    __shared__ int   sself[8];
    __shared__ int   snb[128];
    __shared__ float sd[128];

    const int tid  = threadIdx.x;
    const int base = blockIdx.x * 8;

    if (tid < 8)  sself[tid] = (base + tid < N) ? g_selfi[base + tid] : 0;
    if (tid < 128) {
        int e = base * KNBR + tid;
        snb[tid] = (e < N * KNBR) ? g_nidx[e] : 0;
        sd[tid]  = (e < N * KNBR) ? g_dsq[e]  : 0.f;
    }
    if (tid < 128) { // zero pad cols of bufB once
        bufB[tid * 132 + 128] = 0.f; bufB[tid * 132 + 129] = 0.f;
        bufB[tid * 132 + 130] = 0.f; bufB[tid * 132 + 131] = 0.f;
    }
    __syncthreads();

    // Build X0: [d | h_self(64) | h_neig(64) | 0 pad]
    for (int i = tid; i < 128 * 132; i += 256) {
        int e = i / 132;
        int c = i - e * 132;
        float v;
        if (c == 0)        v = sd[e];
        else if (c < 65)   v = h[sself[e >> 4] * FDIM + (c - 1)];
        else if (c < 129)  v = h[snb[e] * FDIM + (c - 65)];
        else               v = 0.f;
        bufA[i] = v;
    }
    load_w(Wb, We1, 129, 132);
    if (tid < 128) bias[tid] = be1[tid];
    __syncthreads();

    gemm_block<8, true>(bufA, 132, Wb, bias, bufB, 132, 132, 128);
    __syncthreads();

    load_w(Wb, We2, 128, 132);
    if (tid < 128) bias[tid] = be2[tid];
    __syncthreads();

    gemm_block<8, true>(bufB, 132, Wb, bias, bufA, 132, 132, 128);  // bufA = e (X2)
    __syncthreads();

    load_w(Wb, Wc1, 128, 132);
    if (tid < 128) { bias[tid] = bc1[tid]; wc2[tid] = Wc2[tid]; }
    __syncthreads();

    gemm_block<8, true>(bufA, 132, Wb, bias, bufB, 132, 132, 128);  // bufB = c
    __syncthreads();

    // w[e] = c . W_c2 + b_c2
    if (tid < 128) {
        float acc = bc2[0];
        const float* crow = bufB + tid * 132;
#pragma unroll 8
        for (int k = 0; k < 128; ++k) acc = fmaf(crow[k], wc2[k], acc);
        wsh[tid] = acc;
    }

    // e_sum per node
    for (int i = tid; i < 8 * 128; i += 256) {
        int n = i >> 7, c = i & 127;
        float s = 0.f;
#pragma unroll
        for (int e = 0; e < 16; ++e) s += bufA[(n * 16 + e) * 132 + c];
        if (base + n < N) g_esum[(base + n) * HDIM + c] = s;
    }
    __syncthreads();

    // coords_new = coords + mean_k(coord_diff * w)
    if (tid < 24) {
        int n = tid / 3, d = tid - 3 * n;
        int row = base + n;
        if (row < N) {
            float ci = coords[row * 3 + d];
            float s = 0.f;
#pragma unroll
            for (int k = 0; k < 16; ++k) {
                int j = snb[n * 16 + k];
                s += (ci - coords[j * 3 + d]) * wsh[n * 16 + k];
            }
            coords_out[row * 3 + d] = ci + s * (1.f / 16.f);
        }
    }
}

// ---------------- node kernel: 64 nodes per block ----------------
#define NODE_SMEM ((64*196 + 64*132 + 196*128 + 128) * 4)
__global__ void __launch_bounds__(256, 1)
node_kernel(const float* __restrict__ h,
            const float* __restrict__ Wn1, const float* __restrict__ bn1,
            const float* __restrict__ Wn2, const float* __restrict__ bn2,
            float* __restrict__ outp, int N)
{
    extern __shared__ float sm[];
    float* bufA = sm;                 // 64 x 196
    float* bufB = bufA + 64 * 196;    // 64 x 132
    float* Wb   = bufB + 64 * 132;    // 196 x 128
    float* bias = Wb + 196 * 128;     // 128

    __shared__ int sself[64];
    const int tid  = threadIdx.x;
    const int base = blockIdx.x * 64;

    if (tid < 64) sself[tid] = (base + tid < N) ? g_selfi[base + tid] : 0;
    if (tid < 64) {
        bufB[tid * 132 + 128] = 0.f; bufB[tid * 132 + 129] = 0.f;
        bufB[tid * 132 + 130] = 0.f; bufB[tid * 132 + 131] = 0.f;
    }
    __syncthreads();

    for (int i = tid; i < 64 * 196; i += 256) {
        int r = i / 196;
        int c = i - 196 * r;
        int node = base + r;
        float v = 0.f;
        if (node < N) {
            if (c < 128)      v = g_esum[node * HDIM + c];
            else if (c < 192) v = h[sself[r] * FDIM + (c - 128)];
        }
        bufA[i] = v;
    }
    load_w(Wb, Wn1, 192, 196);
    if (tid < 128) bias[tid] = bn1[tid];
    __syncthreads();

    gemm_block<4, true>(bufA, 196, Wb, bias, bufB, 132, 196, 64);
    __syncthreads();

    load_w(Wb, Wn2, 128, 132);
    if (tid < 128) bias[tid] = bn2[tid];
    __syncthreads();

    int valid = N - base; if (valid > 64) valid = 64;
    gemm_block<4, false>(bufB, 132, Wb, bias, outp + base * HDIM, HDIM, 132, valid);
}

// ---------------- launch ----------------
extern "C" void kernel_launch(void* const* d_in, const int* in_sizes, int n_in,
                              void* d_out, int out_size)
{
    const float* h      = (const float*)d_in[0];
    const float* coords = (const float*)d_in[1];
    const int*   rs     = (const int*)  d_in[2];
    const float* We1 = (const float*)d_in[3];
    const float* be1 = (const float*)d_in[4];
    const float* We2 = (const float*)d_in[5];
    const float* be2 = (const float*)d_in[6];
    const float* Wc1 = (const float*)d_in[7];
    const float* bc1 = (const float*)d_in[8];
    const float* Wc2 = (const float*)d_in[9];
    const float* bc2 = (const float*)d_in[10];
    const float* Wn1 = (const float*)d_in[11];
    const float* bn1 = (const float*)d_in[12];
    const float* Wn2 = (const float*)d_in[13];
    const float* bn2 = (const float*)d_in[14];

    const int N   = in_sizes[1] / 3;
    const int nrs = in_sizes[2];

    float* out        = (float*)d_out;               // [N,128]
    float* coords_out = out + (size_t)N * HDIM;      // [N,3]
    float* out_nidx   = coords_out + (size_t)N * 3;  // [N,16] (as float)
    float* out_d      = out_nidx + (size_t)N * KNBR; // [N,16]

    cudaFuncSetAttribute(edge_kernel, cudaFuncAttributeMaxDynamicSharedMemorySize, EDGE_SMEM);
    cudaFuncSetAttribute(node_kernel, cudaFuncAttributeMaxDynamicSharedMemorySize, NODE_SMEM);

    knn_kernel<<<(N + KNN_WARPS - 1) / KNN_WARPS, 256>>>(coords, rs, nrs, N, out_nidx, out_d);
    edge_kernel<<<(N + 7) / 8, 256, EDGE_SMEM>>>(h, coords,
                                                 We1, be1, We2, be2, Wc1, bc1, Wc2, bc2,
                                                 coords_out, N);
    node_kernel<<<(N + 63) / 64, 256, NODE_SMEM>>>(h, Wn1, bn1, Wn2, bn2, out, N);
}

// round 2
// speedup vs baseline: 1.0006x; 1.0006x over previous
#include <cuda_runtime.h>
#include <cstdint>

// Problem constants (fixed by the dataset)
#define MAXN 10000
#define KNBR 16
#define FDIM 64
#define HDIM 128

// ---------------- scratch (no allocations allowed) ----------------
__device__ int   g_nidx[MAXN * KNBR];
__device__ float g_dsq [MAXN * KNBR];
__device__ int   g_selfi[MAXN];
__device__ float g_esum[MAXN * HDIM];

// ---------------- helpers ----------------
__device__ __forceinline__ unsigned long long pk2(float lo, float hi) {
    unsigned long long r;
    asm("mov.b64 %0, {%1, %2};" : "=l"(r) : "f"(lo), "f"(hi));
    return r;
}
__device__ __forceinline__ void upk2(unsigned long long v, float& lo, float& hi) {
    asm("mov.b64 {%0, %1}, %2;" : "=f"(lo), "=f"(hi) : "l"(v));
}
__device__ __forceinline__ void fma2(unsigned long long& d, unsigned long long a, unsigned long long b) {
    asm("fma.rn.f32x2 %0, %1, %2, %0;" : "+l"(d) : "l"(a), "l"(b));
}
__device__ __forceinline__ float selu_f(float x) {
    const float sc = 1.0507009873554805f;
    const float al = 1.6732632423543772f;
    return x > 0.f ? sc * x : sc * al * expm1f(x);
}

// ---------------- KNN: one warp per row, exact (d2, idx) ordering ----------------
#define KNN_WARPS 8
__global__ void knn_kernel(const float* __restrict__ coords,
                           const int* __restrict__ rs, int nrs, int N,
                           float* __restrict__ out_nidx_f, float* __restrict__ out_d)
{
    __shared__ unsigned long long mg[KNN_WARPS][17 * 32];
    const int w    = threadIdx.x >> 5;
    const int lane = threadIdx.x & 31;
    const int row  = blockIdx.x * KNN_WARPS + w;
    if (row >= N) return;

    int s0 = 0, s1 = N;
    for (int s = 0; s + 1 < nrs; ++s) {
        int a = rs[s], b = rs[s + 1];
        if (a <= row && row < b) { s0 = a; s1 = b; }
    }

    const float xi = coords[row * 3 + 0];
    const float yi = coords[row * 3 + 1];
    const float zi = coords[row * 3 + 2];
    const float ni = __fadd_rn(__fadd_rn(__fmul_rn(xi, xi), __fmul_rn(yi, yi)), __fmul_rn(zi, zi));

    unsigned long long a[17];
#pragma unroll
    for (int t = 0; t < 17; ++t) a[t] = 0xFFFFFFFFFFFFFFFFull;

    for (int j = s0 + lane; j < s1; j += 32) {
        const float xj = coords[j * 3 + 0];
        const float yj = coords[j * 3 + 1];
        const float zj = coords[j * 3 + 2];
        const float nj  = __fadd_rn(__fadd_rn(__fmul_rn(xj, xj), __fmul_rn(yj, yj)), __fmul_rn(zj, zj));
        const float dot = __fadd_rn(__fadd_rn(__fmul_rn(xi, xj), __fmul_rn(yi, yj)), __fmul_rn(zi, zj));
        float d2 = __fadd_rn(__fadd_rn(ni, nj), __fmul_rn(-2.f, dot));
        d2 = fmaxf(d2, 0.f);
        unsigned long long key =
            ((unsigned long long)__float_as_uint(d2) << 32) | (unsigned)j;
        if (key < a[16]) {
            unsigned long long cur = key;
#pragma unroll
            for (int t = 0; t < 17; ++t) {
                if (cur < a[t]) { unsigned long long tmp = a[t]; a[t] = cur; cur = tmp; }
            }
        }
    }

#pragma unroll
    for (int t = 0; t < 17; ++t) mg[w][lane * 17 + t] = a[t];
    __syncwarp();

    int head = 0;
    for (int t = 0; t < 17; ++t) {
        unsigned long long v = mg[w][lane * 17 + head];
        unsigned long long m = v;
#pragma unroll
        for (int off = 16; off >= 1; off >>= 1) {
            unsigned long long o = __shfl_xor_sync(0xffffffffu, m, off);
            if (o < m) m = o;
        }
        unsigned ball = __ballot_sync(0xffffffffu, v == m);
        int win = __ffs(ball) - 1;
        if (lane == win) head++;
        if (lane == 0) {
            unsigned jj = (unsigned)(m & 0xffffffffu);
            float dd = __uint_as_float((unsigned)(m >> 32));
            if (t == 0) {
                g_selfi[row] = (int)jj;
            } else {
                g_nidx[row * KNBR + t - 1] = (int)jj;
                g_dsq [row * KNBR + t - 1] = dd;
                out_nidx_f[row * KNBR + t - 1] = (float)(int)jj;
                out_d    [row * KNBR + t - 1] = dd;
            }
        }
    }
}

// ---------------- block GEMM (f32x2 packed), operands in smem ----------------
// Computes O[m][n0..n0+7] for 128-col output; A [M x kp] (lda), W [kp x 128] smem,
// bias[128] smem, optional SELU. 256 threads: 16x16 grid, RPT rows x 8 cols/thread.
template<int RPT, bool DO_SELU>
__device__ __forceinline__ void gemm_block(const float* __restrict__ A, int lda,
                                           const float* __restrict__ W,
                                           const float* __restrict__ bias,
                                           float* __restrict__ O, int ldo,
                                           int kp, int valid)
{
    const int tx = threadIdx.x & 15;
    const int ty = threadIdx.x >> 4;
    const int n0 = tx * 8;
    const int m0 = ty * RPT;

    unsigned long long acc[RPT][4];
#pragma unroll
    for (int i = 0; i < RPT; ++i)
#pragma unroll
        for (int j = 0; j < 4; ++j)
            acc[i][j] = pk2(bias[n0 + 2 * j], bias[n0 + 2 * j + 1]);

    const float* Ap = A + m0 * lda;
    for (int k = 0; k < kp; k += 4) {
        float4 av[RPT];
#pragma unroll
        for (int i = 0; i < RPT; ++i)
            av[i] = *reinterpret_cast<const float4*>(Ap + i * lda + k);
#pragma unroll
        for (int r = 0; r < 4; ++r) {
            const float* wr = W + (k + r) * 128 + n0;
            ulonglong2 b0 = *reinterpret_cast<const ulonglong2*>(wr);
            ulonglong2 b1 = *reinterpret_cast<const ulonglong2*>(wr + 4);
#pragma unroll
            for (int i = 0; i < RPT; ++i) {
                float a_ = (r == 0) ? av[i].x : (r == 1) ? av[i].y : (r == 2) ? av[i].z : av[i].w;
                unsigned long long aa = pk2(a_, a_);
                fma2(acc[i][0], aa, b0.x);
                fma2(acc[i][1], aa, b0.y);
                fma2(acc[i][2], aa, b1.x);
                fma2(acc[i][3], aa, b1.y);
            }
        }
    }

#pragma unroll
    for (int i = 0; i < RPT; ++i) {
        int row = m0 + i;
        if (row < valid) {
            float o[8];
#pragma unroll
            for (int j = 0; j < 4; ++j) { upk2(acc[i][j], o[2 * j], o[2 * j + 1]); }
            if (DO_SELU) {
#pragma unroll
                for (int j = 0; j < 8; ++j) o[j] = selu_f(o[j]);
            }
            *reinterpret_cast<float4*>(O + row * ldo + n0)     = make_float4(o[0], o[1], o[2], o[3]);
            *reinterpret_cast<float4*>(O + row * ldo + n0 + 4) = make_float4(o[4], o[5], o[6], o[7]);
        }
    }
}

__device__ __forceinline__ void load_w(float* Wb, const float* __restrict__ Wg, int rows, int kp)
{
    const int tid = threadIdx.x;
    const int n4 = (rows * 128) >> 2;
    for (int i = tid; i < n4; i += 256)
        reinterpret_cast<float4*>(Wb)[i] = reinterpret_cast<const float4*>(Wg)[i];
    for (int i = tid; i < (kp - rows) * 128; i += 256)
        Wb[rows * 128 + i] = 0.f;
}

// ---------------- edge kernel: 8 nodes (128 edges) per block ----------------
#define EDGE_SMEM ((128*132*2 + 132*128 + 128*3) * 4)
__global__ void __launch_bounds__(256, 1)
edge_kernel(const float* __restrict__ h, const float* __restrict__ coords,
            const float* __restrict__ We1, const float* __restrict__ be1,
            const float* __restrict__ We2, const float* __restrict__ be2,
            const float* __restrict__ Wc1, const float* __restrict__ bc1,
            const float* __restrict__ Wc2, const float* __restrict__ bc2,
            float* __restrict__ coords_out, int N)
{
    extern __shared__ float sm[];
    float* bufA = sm;                 // 128 x 132
    float* bufB = bufA + 128 * 132;   // 128 x 132
    float* Wb   = bufB + 128 * 132;   // 132 x 128
    float* bias = Wb + 132 * 128;     // 128
    float* wc2  = bias + 128;         // 128
    float* wsh  = wc2 + 128;          // 128

    __shared__ int   sself[8];
    __shared__ int   snb[128];
    __shared__ float sd[128];

    const int tid  = threadIdx.x;
    const int base = blockIdx.x * 8;

    if (tid < 8)  sself[tid] = (base + tid < N) ? g_selfi[base + tid] : 0;
    if (tid < 128) {
        int e = base * KNBR + tid;
        snb[tid] = (e < N * KNBR) ? g_nidx[e] : 0;
        sd[tid]  = (e < N * KNBR) ? g_dsq[e]  : 0.f;
    }
    if (tid < 128) { // zero pad cols of bufB once
        bufB[tid * 132 + 128] = 0.f; bufB[tid * 132 + 129] = 0.f;
        bufB[tid * 132 + 130] = 0.f; bufB[tid * 132 + 131] = 0.f;
    }
    __syncthreads();

    // Build X0: [d | h_self(64) | h_neig(64) | 0 pad]
    for (int i = tid; i < 128 * 132; i += 256) {
        int e = i / 132;
        int c = i - e * 132;
        float v;
        if (c == 0)        v = sd[e];
        else if (c < 65)   v = h[sself[e >> 4] * FDIM + (c - 1)];
        else if (c < 129)  v = h[snb[e] * FDIM + (c - 65)];
        else               v = 0.f;
        bufA[i] = v;
    }
    load_w(Wb, We1, 129, 132);
    if (tid < 128) bias[tid] = be1[tid];
    __syncthreads();

    gemm_block<8, true>(bufA, 132, Wb, bias, bufB, 132, 132, 128);
    __syncthreads();

    load_w(Wb, We2, 128, 132);
    if (tid < 128) bias[tid] = be2[tid];
    __syncthreads();

    gemm_block<8, true>(bufB, 132, Wb, bias, bufA, 132, 132, 128);  // bufA = e (X2)
    __syncthreads();

    load_w(Wb, Wc1, 128, 132);
    if (tid < 128) { bias[tid] = bc1[tid]; wc2[tid] = Wc2[tid]; }
    __syncthreads();

    gemm_block<8, true>(bufA, 132, Wb, bias, bufB, 132, 132, 128);  // bufB = c
    __syncthreads();

    // w[e] = c . W_c2 + b_c2
    if (tid < 128) {
        float acc = bc2[0];
        const float* crow = bufB + tid * 132;
#pragma unroll 8
        for (int k = 0; k < 128; ++k) acc = fmaf(crow[k], wc2[k], acc);
        wsh[tid] = acc;
    }

    // e_sum per node
    for (int i = tid; i < 8 * 128; i += 256) {
        int n = i >> 7, c = i & 127;
        float s = 0.f;
#pragma unroll
        for (int e = 0; e < 16; ++e) s += bufA[(n * 16 + e) * 132 + c];
        if (base + n < N) g_esum[(base + n) * HDIM + c] = s;
    }
    __syncthreads();

    // coords_new = coords + mean_k(coord_diff * w)
    if (tid < 24) {
        int n = tid / 3, d = tid - 3 * n;
        int row = base + n;
        if (row < N) {
            float ci = coords[row * 3 + d];
            float s = 0.f;
#pragma unroll
            for (int k = 0; k < 16; ++k) {
                int j = snb[n * 16 + k];
                s += (ci - coords[j * 3 + d]) * wsh[n * 16 + k];
            }
            coords_out[row * 3 + d] = ci + s * (1.f / 16.f);
        }
    }
}

// ---------------- node kernel: 64 nodes per block ----------------
#define NODE_SMEM ((64*196 + 64*132 + 196*128 + 128) * 4)
__global__ void __launch_bounds__(256, 1)
node_kernel(const float* __restrict__ h,
            const float* __restrict__ Wn1, const float* __restrict__ bn1,
            const float* __restrict__ Wn2, const float* __restrict__ bn2,
            float* __restrict__ outp, int N)
{
    extern __shared__ float sm[];
    float* bufA = sm;                 // 64 x 196
    float* bufB = bufA + 64 * 196;    // 64 x 132
    float* Wb   = bufB + 64 * 132;    // 196 x 128
    float* bias = Wb + 196 * 128;     // 128

    __shared__ int sself[64];
    const int tid  = threadIdx.x;
    const int base = blockIdx.x * 64;

    if (tid < 64) sself[tid] = (base + tid < N) ? g_selfi[base + tid] : 0;
    if (tid < 64) {
        bufB[tid * 132 + 128] = 0.f; bufB[tid * 132 + 129] = 0.f;
        bufB[tid * 132 + 130] = 0.f; bufB[tid * 132 + 131] = 0.f;
    }
    __syncthreads();

    for (int i = tid; i < 64 * 196; i += 256) {
        int r = i / 196;
        int c = i - 196 * r;
        int node = base + r;
        float v = 0.f;
        if (node < N) {
            if (c < 128)      v = g_esum[node * HDIM + c];
            else if (c < 192) v = h[sself[r] * FDIM + (c - 128)];
        }
        bufA[i] = v;
    }
    load_w(Wb, Wn1, 192, 196);
    if (tid < 128) bias[tid] = bn1[tid];
    __syncthreads();

    gemm_block<4, true>(bufA, 196, Wb, bias, bufB, 132, 196, 64);
    __syncthreads();

    load_w(Wb, Wn2, 128, 132);
    if (tid < 128) bias[tid] = bn2[tid];
    __syncthreads();

    int valid = N - base; if (valid > 64) valid = 64;
    gemm_block<4, false>(bufB, 132, Wb, bias, outp + base * HDIM, HDIM, 132, valid);
}

// ---------------- launch ----------------
extern "C" void kernel_launch(void* const* d_in, const int* in_sizes, int n_in,
                              void* d_out, int out_size)
{
    const float* h      = (const float*)d_in[0];
    const float* coords = (const float*)d_in[1];
    const int*   rs     = (const int*)  d_in[2];
    const float* We1 = (const float*)d_in[3];
    const float* be1 = (const float*)d_in[4];
    const float* We2 = (const float*)d_in[5];
    const float* be2 = (const float*)d_in[6];
    const float* Wc1 = (const float*)d_in[7];
    const float* bc1 = (const float*)d_in[8];
    const float* Wc2 = (const float*)d_in[9];
    const float* bc2 = (const float*)d_in[10];
    const float* Wn1 = (const float*)d_in[11];
    const float* bn1 = (const float*)d_in[12];
    const float* Wn2 = (const float*)d_in[13];
    const float* bn2 = (const float*)d_in[14];

    const int N   = in_sizes[1] / 3;
    const int nrs = in_sizes[2];

    float* out        = (float*)d_out;               // [N,128]
    float* coords_out = out + (size_t)N * HDIM;      // [N,3]
    float* out_nidx   = coords_out + (size_t)N * 3;  // [N,16] (as float)
    float* out_d      = out_nidx + (size_t)N * KNBR; // [N,16]

    cudaFuncSetAttribute(edge_kernel, cudaFuncAttributeMaxDynamicSharedMemorySize, EDGE_SMEM);
    cudaFuncSetAttribute(node_kernel, cudaFuncAttributeMaxDynamicSharedMemorySize, NODE_SMEM);

    knn_kernel<<<(N + KNN_WARPS - 1) / KNN_WARPS, 256>>>(coords, rs, nrs, N, out_nidx, out_d);
    edge_kernel<<<(N + 7) / 8, 256, EDGE_SMEM>>>(h, coords,
                                                 We1, be1, We2, be2, Wc1, bc1, Wc2, bc2,
                                                 coords_out, N);
    node_kernel<<<(N + 63) / 64, 256, NODE_SMEM>>>(h, Wn1, bn1, Wn2, bn2, out, N);
}